// round 13
// baseline (speedup 1.0000x reference)
#include <cuda_runtime.h>
#include <cuda_fp16.h>
#include <cuda_bf16.h>

#define MAXN 100000
#define MAXE 1600000
#define F 64

// ---------------- scratch (static device globals; no allocation) -------------
// Invariant: at entry of every kernel_launch call, d_counts == 0,
// d_scanstate == 0, d_ticket == 0 (true at module load; every call restores).
__device__ int      d_counts[MAXN];        // degree histogram (zeroed by scan)
__device__ int      d_rowptr[MAXN + 1];    // CSR row pointers (by destination)
__device__ int      d_cursor[MAXN];        // scatter cursors
__device__ float    d_dinv[MAXN];          // deg^-1/2
__device__ unsigned long long d_scanstate[512];  // lookback {status:2,val:62}
__device__ unsigned d_ticket;              // scan block ordering ticket
__device__ int      d_edgesrc[MAXE + MAXN];// CSR-by-dst: source index per slot
__device__ unsigned d_xh[MAXN * 32];       // dinv-scaled x, fp16 (32 half2/node)
__device__ unsigned d_ax[MAXN * 32];       // aggregation output (fp16)
__device__ unsigned d_gh[MAXN * 32];       // dinv-scaled layer-1 act (fp16)

__device__ __forceinline__ unsigned h2_bits(__half2 h) {
    union { __half2 h; unsigned u; } cvt;
    cvt.h = h;
    return cvt.u;
}

// ---------------- edge index accessors (runtime dtype) ------------------------
// per-warp dtype detect: int64 indices < 2^31 have zero odd 32-bit words.
__device__ __forceinline__ int detect64(const void* ei, int lane) {
    const unsigned* p = (const unsigned*)ei;
    unsigned v = (lane < 16) ? p[2 * lane + 1] : 0u;
    return __all_sync(0xffffffffu, v == 0u);
}

__device__ __forceinline__ int edge_at(const void* ei, long long idx, int is64) {
    if (is64) return (int)((const long long*)ei)[idx];
    return ((const int*)ei)[idx];
}

__device__ __forceinline__ int2 edge_pair(const void* ei, long long halfidx,
                                          int is64) {
    if (is64) {
        longlong2 v = ((const longlong2*)ei)[halfidx];
        return make_int2((int)v.x, (int)v.y);
    }
    return ((const int2*)ei)[halfidx];
}

// ---------------- hist: degree histogram of destinations, 2 edges/thread -----
__global__ void k_hist(const void* __restrict__ ei, int E) {
    int lane = threadIdx.x & 31;
    int is64 = detect64(ei, lane);
    int e = (blockIdx.x * blockDim.x + threadIdx.x) * 2;
    if (e + 1 < E) {
        int2 c = edge_pair(ei, ((long long)E + e) >> 1, is64);
        atomicAdd(&d_counts[c.x], 1);
        atomicAdd(&d_counts[c.y], 1);
    } else if (e < E) {
        atomicAdd(&d_counts[edge_at(ei, (long long)E + e, is64)], 1);
    }
}

// single-pass scan (decoupled lookback) + fused dinv + counts re-zeroing.
// v = counts[i] + 1 (self loop folded here; counts arrive zero-based).
__global__ void k_scan(int n, int nb, int total) {  // 512 threads/block
    __shared__ unsigned sbid;
    __shared__ int srun;
    __shared__ int ws[16];
    if (threadIdx.x == 0) sbid = atomicAdd(&d_ticket, 1u);
    __syncthreads();
    int bid = (int)sbid;
    int i = bid * 512 + threadIdx.x;
    int lane = threadIdx.x & 31;
    int v = (i < n) ? (d_counts[i] + 1) : 0;
    if (i < n) {
        d_dinv[i] = rsqrtf((float)v);
        d_counts[i] = 0;  // restore invariant for next call
    }
    int x = v;
    #pragma unroll
    for (int d = 1; d < 32; d <<= 1) {
        int y = __shfl_up_sync(0xffffffffu, x, d);
        if (lane >= d) x += y;
    }
    if (lane == 31) ws[threadIdx.x >> 5] = x;
    __syncthreads();
    if (threadIdx.x < 16) {
        int z = ws[threadIdx.x];
        #pragma unroll
        for (int d = 1; d < 16; d <<= 1) {
            int y = __shfl_up_sync(0xffffu, z, d);
            if ((int)threadIdx.x >= d) z += y;
        }
        ws[threadIdx.x] = z;
    }
    __syncthreads();
    int off = (threadIdx.x >= 32) ? ws[(threadIdx.x >> 5) - 1] : 0;
    int incl = x + off;

    if (threadIdx.x == 511) {
        int btotal = incl;
        if (bid == 0) {
            atomicExch(&d_scanstate[0],
                       (2ull << 62) | (unsigned long long)(unsigned)btotal);
            srun = 0;
        } else {
            atomicExch(&d_scanstate[bid],
                       (1ull << 62) | (unsigned long long)(unsigned)btotal);
            int running = 0;
            int j = bid - 1;
            while (true) {
                unsigned long long s;
                do {
                    s = *(volatile unsigned long long*)&d_scanstate[j];
                } while ((s >> 62) == 0ull);
                int val = (int)(s & 0xffffffffull);
                running += val;
                if ((s >> 62) == 2ull) break;
                j--;
            }
            atomicExch(&d_scanstate[bid],
                       (2ull << 62) | (unsigned long long)(unsigned)(running + btotal));
            srun = running;
        }
    }
    __syncthreads();
    int run = srun;
    if (i < n) {
        int r = incl - v + run;
        d_rowptr[i] = r;
        d_cursor[i] = r;
    }
    if (i == 0) d_rowptr[n] = total;
}

// fused: scatter src indices (blocks [0,nbSc)) + dinv-scaled x->fp16 (rest).
// Block 0 additionally re-zeroes scanstate + ticket (scan is complete).
__global__ void k_scatxh(const void* __restrict__ ei, const float* __restrict__ x,
                         int E, int n, int nbSc, int n16) {
    int b = blockIdx.x;
    if (b == 0) {
        for (int i = threadIdx.x; i < 512; i += 256) d_scanstate[i] = 0ull;
        if (threadIdx.x == 0) d_ticket = 0u;
    }
    if (b < nbSc) {
        int lane = threadIdx.x & 31;
        int is64 = detect64(ei, lane);
        int idx = b * 256 + threadIdx.x;
        int Eh = (E + 1) >> 1;
        if (idx < Eh) {
            int e = idx * 2;
            if (e + 1 < E) {
                int2 r = edge_pair(ei, (long long)e >> 1, is64);
                int2 c = edge_pair(ei, ((long long)E + e) >> 1, is64);
                int p0 = atomicAdd(&d_cursor[c.x], 1);
                d_edgesrc[p0] = r.x;
                int p1 = atomicAdd(&d_cursor[c.y], 1);
                d_edgesrc[p1] = r.y;
            } else {
                int r = edge_at(ei, e, is64);
                int c = edge_at(ei, (long long)E + e, is64);
                int pos = atomicAdd(&d_cursor[c], 1);
                d_edgesrc[pos] = r;
            }
        } else if (idx < Eh + n) {
            int i = idx - Eh;
            int pos = atomicAdd(&d_cursor[i], 1);
            d_edgesrc[pos] = i;
        }
    } else {
        int i = (b - nbSc) * 256 + threadIdx.x;  // float4 index
        if (i < n16) {
            float di = d_dinv[i >> 4];
            float4 v = ((const float4*)x)[i];
            uint2 w;
            w.x = h2_bits(__floats2half2_rn(di * v.x, di * v.y));
            w.y = h2_bits(__floats2half2_rn(di * v.z, di * v.w));
            ((uint2*)d_xh)[i] = w;
        }
    }
}

// ---------------- aggregation: d_ax[c] = dinv[c] * sum_{e->c} S[src_e] -------
// warp per node. Indices staged 32-at-a-time via ONE coalesced lane-parallel
// load, broadcast by shfl -> gathers have no memory dependency in their chain
// and issue back-to-back (4 in flight).
template <bool SECOND>
__global__ void k_agg(int n) {
    int gwarp = (blockIdx.x * blockDim.x + threadIdx.x) >> 5;
    if (gwarp >= n) return;
    int lane = threadIdx.x & 31;
    int s = d_rowptr[gwarp];
    int e = d_rowptr[gwarp + 1];
    const __half2* H2 = (const __half2*)(SECOND ? d_gh : d_xh);
    float ax = 0.f, ay = 0.f;
    for (int base = s; base < e; base += 32) {
        int t = base + lane;
        int myidx = (t < e) ? d_edgesrc[t] : 0;
        int cnt = e - base;
        if (cnt > 32) cnt = 32;
        int k = 0;
        for (; k + 3 < cnt; k += 4) {
            int s0 = __shfl_sync(0xffffffffu, myidx, k);
            int s1 = __shfl_sync(0xffffffffu, myidx, k + 1);
            int s2 = __shfl_sync(0xffffffffu, myidx, k + 2);
            int s3 = __shfl_sync(0xffffffffu, myidx, k + 3);
            float2 h0 = __half22float2(H2[s0 * 32 + lane]);
            float2 h1 = __half22float2(H2[s1 * 32 + lane]);
            float2 h2 = __half22float2(H2[s2 * 32 + lane]);
            float2 h3 = __half22float2(H2[s3 * 32 + lane]);
            ax += h0.x + h1.x + h2.x + h3.x;
            ay += h0.y + h1.y + h2.y + h3.y;
        }
        for (; k < cnt; k++) {
            int s0 = __shfl_sync(0xffffffffu, myidx, k);
            float2 h0 = __half22float2(H2[s0 * 32 + lane]);
            ax += h0.x;
            ay += h0.y;
        }
    }
    float di = d_dinv[gwarp];
    d_ax[gwarp * 32 + lane] = h2_bits(__floats2half2_rn(di * ax, di * ay));
}

// ---------------- GEMM via tensor cores (HMMA m16n8k16) ----------------------
// reads d_ax (fp16), computes d_ax@W + b; RELU=true -> dinv*relu, fp16 to
// d_gh; RELU=false -> fp32 to OUT. 256 threads, 128 nodes/block.
#define XS_PITCH 72
template <bool RELU>
__global__ __launch_bounds__(256) void k_gemm(const float* __restrict__ W,
                                              const float* __restrict__ bias,
                                              float* __restrict__ OUT, int n) {
    __shared__ __half Xs[128 * XS_PITCH];  // 18 KB
    __shared__ __half Wt[64 * XS_PITCH];   // 9 KB, Wt[f][k] = W[k][f]
    int t = threadIdx.x;
    int base = blockIdx.x * 128;

    // X tile fill via cp.async: 128 nodes * 8 uint4 = 1024, 4 per thread
    for (int i = t; i < 1024; i += 256) {
        int node = i >> 3, q = i & 7;
        void* dst = &Xs[node * XS_PITCH + q * 8];
        if (base + node < n) {
            unsigned ds = (unsigned)__cvta_generic_to_shared(dst);
            const uint4* src = (const uint4*)&d_ax[(base + node) * 32 + q * 4];
            asm volatile("cp.async.ca.shared.global [%0], [%1], 16;"
                         :: "r"(ds), "l"(src));
        } else {
            *(uint4*)dst = make_uint4(0, 0, 0, 0);
        }
    }
    asm volatile("cp.async.commit_group;");
    // W[64,64] fp32 -> Wt fp16 transposed (overlaps with cp.async)
    for (int i = t; i < 4096; i += 256) {
        int k = i >> 6, f = i & 63;
        Wt[f * XS_PITCH + k] = __float2half(W[k * 64 + f]);
    }
    asm volatile("cp.async.wait_group 0;");
    __syncthreads();

    int warp = t >> 5, lane = t & 31;
    int gid = lane >> 2, tig = lane & 3;
    int mbase = warp * 16;

    float c[8][4];
    #pragma unroll
    for (int nt = 0; nt < 8; nt++)
        #pragma unroll
        for (int q = 0; q < 4; q++) c[nt][q] = 0.f;

    #pragma unroll
    for (int kt = 0; kt < 4; kt++) {
        int k0 = kt * 16 + 2 * tig;
        unsigned a0 = *(const unsigned*)&Xs[(mbase + gid) * XS_PITCH + k0];
        unsigned a1 = *(const unsigned*)&Xs[(mbase + gid + 8) * XS_PITCH + k0];
        unsigned a2 = *(const unsigned*)&Xs[(mbase + gid) * XS_PITCH + k0 + 8];
        unsigned a3 = *(const unsigned*)&Xs[(mbase + gid + 8) * XS_PITCH + k0 + 8];
        #pragma unroll
        for (int nt = 0; nt < 8; nt++) {
            unsigned b0 = *(const unsigned*)&Wt[(nt * 8 + gid) * XS_PITCH + k0];
            unsigned b1 = *(const unsigned*)&Wt[(nt * 8 + gid) * XS_PITCH + k0 + 8];
            asm volatile(
                "mma.sync.aligned.m16n8k16.row.col.f32.f16.f16.f32 "
                "{%0,%1,%2,%3}, {%4,%5,%6,%7}, {%8,%9}, {%0,%1,%2,%3};"
                : "+f"(c[nt][0]), "+f"(c[nt][1]), "+f"(c[nt][2]), "+f"(c[nt][3])
                : "r"(a0), "r"(a1), "r"(a2), "r"(a3), "r"(b0), "r"(b1));
        }
    }

    // epilogue: +bias (, relu*dinv); c0,c1 = row gid, c2,c3 = row gid+8
    int node = base + mbase + gid;
    float di0 = (RELU && node < n) ? d_dinv[node] : 0.f;
    float di8 = (RELU && node + 8 < n) ? d_dinv[node + 8] : 0.f;
    #pragma unroll
    for (int nt = 0; nt < 8; nt++) {
        int word = nt * 4 + tig;  // half2/float2 word = features {2w, 2w+1}
        float2 bb = __ldg(&((const float2*)bias)[word]);
        float v0 = c[nt][0] + bb.x, v1 = c[nt][1] + bb.y;
        float v2 = c[nt][2] + bb.x, v3 = c[nt][3] + bb.y;
        if (RELU) {
            v0 = fmaxf(v0, 0.f) * di0; v1 = fmaxf(v1, 0.f) * di0;
            v2 = fmaxf(v2, 0.f) * di8; v3 = fmaxf(v3, 0.f) * di8;
            if (node < n)
                d_gh[node * 32 + word] = h2_bits(__floats2half2_rn(v0, v1));
            if (node + 8 < n)
                d_gh[(node + 8) * 32 + word] = h2_bits(__floats2half2_rn(v2, v3));
        } else {
            if (node < n)
                ((float2*)OUT)[node * 32 + word] = make_float2(v0, v1);
            if (node + 8 < n)
                ((float2*)OUT)[(node + 8) * 32 + word] = make_float2(v2, v3);
        }
    }
}

// ---------------- launch -----------------------------------------------------
extern "C" void kernel_launch(void* const* d_in, const int* in_sizes, int n_in,
                              void* d_out, int out_size) {
    const float* x = (const float*)d_in[0];
    const void* ei = d_in[1];
    const float* W1 = (const float*)d_in[2];
    const float* b1 = (const float*)d_in[3];
    const float* W2 = (const float*)d_in[4];
    const float* b2 = (const float*)d_in[5];
    float* out = (float*)d_out;

    int N = in_sizes[0] / F;          // 100000
    int E = in_sizes[1] / 2;          // 1600000
    int nbS = (N + 511) / 512;        // 196 scan blocks
    int Eh = (E + 1) / 2;
    int nbH = (Eh + 255) / 256;       // hist blocks (2 edges/thread)
    int nbSc = (Eh + N + 255) / 256;  // scatter blocks
    int nbX = (N * 16 + 255) / 256;   // xh blocks

    // graph build (3 kernels; no init — state recycled across calls)
    k_hist<<<nbH, 256>>>(ei, E);
    k_scan<<<nbS, 512>>>(N, nbS, E + N);
    k_scatxh<<<nbSc + nbX, 256>>>(ei, x, E, N, nbSc, N * 16);

    // layer 1: AX = dinv*agg(xh); gh = dinv*relu(AX@W1 + b1)
    k_agg<false><<<(N * 32 + 255) / 256, 256>>>(N);   // profiled slot 4
    k_gemm<true><<<(N + 127) / 128, 256>>>(W1, b1, out /*unused*/, N);

    // layer 2: Ag = dinv*agg(gh); out = Ag@W2 + b2
    k_agg<true><<<(N * 32 + 255) / 256, 256>>>(N);
    k_gemm<false><<<(N + 127) / 128, 256>>>(W2, b2, out, N);
}

// round 14
// speedup vs baseline: 1.0824x; 1.0824x over previous
#include <cuda_runtime.h>
#include <cuda_fp16.h>
#include <cuda_bf16.h>

#define MAXN 100000
#define MAXE 1600000
#define F 64

// ---------------- scratch (static device globals; no allocation) -------------
// Invariant: at entry of every kernel_launch call, d_counts == 0,
// d_scanstate == 0, d_ticket == 0 (true at module load; every call restores).
__device__ int      d_counts[MAXN];        // degree histogram (zeroed by scan)
__device__ int      d_rowptr[MAXN + 1];    // CSR row pointers (by destination)
__device__ int      d_cursor[MAXN];        // scatter cursors
__device__ float    d_dinv[MAXN];          // deg^-1/2
__device__ unsigned long long d_scanstate[512];  // lookback {status:2,val:62}
__device__ unsigned d_ticket;              // scan block ordering ticket
__device__ int      d_edgesrc[MAXE + MAXN];// CSR-by-dst: source index per slot
__device__ unsigned d_xh[MAXN * 32];       // dinv-scaled x, fp16 (32 half2/node)
__device__ unsigned d_ax[MAXN * 32];       // aggregation output (fp16)
__device__ unsigned d_gh[MAXN * 32];       // dinv-scaled layer-1 act (fp16)

__device__ __forceinline__ unsigned h2_bits(__half2 h) {
    union { __half2 h; unsigned u; } cvt;
    cvt.h = h;
    return cvt.u;
}

// ---------------- edge index accessors (runtime dtype) ------------------------
// per-warp dtype detect: int64 indices < 2^31 have zero odd 32-bit words.
__device__ __forceinline__ int detect64(const void* ei, int lane) {
    const unsigned* p = (const unsigned*)ei;
    unsigned v = (lane < 16) ? p[2 * lane + 1] : 0u;
    return __all_sync(0xffffffffu, v == 0u);
}

__device__ __forceinline__ int edge_at(const void* ei, long long idx, int is64) {
    if (is64) return (int)((const long long*)ei)[idx];
    return ((const int*)ei)[idx];
}

__device__ __forceinline__ int2 edge_pair(const void* ei, long long halfidx,
                                          int is64) {
    if (is64) {
        longlong2 v = ((const longlong2*)ei)[halfidx];
        return make_int2((int)v.x, (int)v.y);
    }
    return ((const int2*)ei)[halfidx];
}

// ---------------- hist: degree histogram of destinations, 2 edges/thread -----
__global__ void k_hist(const void* __restrict__ ei, int E) {
    int lane = threadIdx.x & 31;
    int is64 = detect64(ei, lane);
    int e = (blockIdx.x * blockDim.x + threadIdx.x) * 2;
    if (e + 1 < E) {
        int2 c = edge_pair(ei, ((long long)E + e) >> 1, is64);
        atomicAdd(&d_counts[c.x], 1);
        atomicAdd(&d_counts[c.y], 1);
    } else if (e < E) {
        atomicAdd(&d_counts[edge_at(ei, (long long)E + e, is64)], 1);
    }
}

// single-pass scan (decoupled lookback) + fused dinv + counts re-zeroing.
// v = counts[i] + 1 (self loop folded here; counts arrive zero-based).
__global__ void k_scan(int n, int nb, int total) {  // 512 threads/block
    __shared__ unsigned sbid;
    __shared__ int srun;
    __shared__ int ws[16];
    if (threadIdx.x == 0) sbid = atomicAdd(&d_ticket, 1u);
    __syncthreads();
    int bid = (int)sbid;
    int i = bid * 512 + threadIdx.x;
    int lane = threadIdx.x & 31;
    int v = (i < n) ? (d_counts[i] + 1) : 0;
    if (i < n) {
        d_dinv[i] = rsqrtf((float)v);
        d_counts[i] = 0;  // restore invariant for next call
    }
    int x = v;
    #pragma unroll
    for (int d = 1; d < 32; d <<= 1) {
        int y = __shfl_up_sync(0xffffffffu, x, d);
        if (lane >= d) x += y;
    }
    if (lane == 31) ws[threadIdx.x >> 5] = x;
    __syncthreads();
    if (threadIdx.x < 16) {
        int z = ws[threadIdx.x];
        #pragma unroll
        for (int d = 1; d < 16; d <<= 1) {
            int y = __shfl_up_sync(0xffffu, z, d);
            if ((int)threadIdx.x >= d) z += y;
        }
        ws[threadIdx.x] = z;
    }
    __syncthreads();
    int off = (threadIdx.x >= 32) ? ws[(threadIdx.x >> 5) - 1] : 0;
    int incl = x + off;

    if (threadIdx.x == 511) {
        int btotal = incl;
        if (bid == 0) {
            atomicExch(&d_scanstate[0],
                       (2ull << 62) | (unsigned long long)(unsigned)btotal);
            srun = 0;
        } else {
            atomicExch(&d_scanstate[bid],
                       (1ull << 62) | (unsigned long long)(unsigned)btotal);
            int running = 0;
            int j = bid - 1;
            while (true) {
                unsigned long long s;
                do {
                    s = *(volatile unsigned long long*)&d_scanstate[j];
                } while ((s >> 62) == 0ull);
                int val = (int)(s & 0xffffffffull);
                running += val;
                if ((s >> 62) == 2ull) break;
                j--;
            }
            atomicExch(&d_scanstate[bid],
                       (2ull << 62) | (unsigned long long)(unsigned)(running + btotal));
            srun = running;
        }
    }
    __syncthreads();
    int run = srun;
    if (i < n) {
        int r = incl - v + run;
        d_rowptr[i] = r;
        d_cursor[i] = r;
    }
    if (i == 0) d_rowptr[n] = total;
}

// fused: scatter src indices (blocks [0,nbSc)) + dinv-scaled x->fp16 (rest).
// Block 0 additionally re-zeroes scanstate + ticket (scan is complete).
__global__ void k_scatxh(const void* __restrict__ ei, const float* __restrict__ x,
                         int E, int n, int nbSc, int n16) {
    int b = blockIdx.x;
    if (b == 0) {
        for (int i = threadIdx.x; i < 512; i += 256) d_scanstate[i] = 0ull;
        if (threadIdx.x == 0) d_ticket = 0u;
    }
    if (b < nbSc) {
        int lane = threadIdx.x & 31;
        int is64 = detect64(ei, lane);
        int idx = b * 256 + threadIdx.x;
        int Eh = (E + 1) >> 1;
        if (idx < Eh) {
            int e = idx * 2;
            if (e + 1 < E) {
                int2 r = edge_pair(ei, (long long)e >> 1, is64);
                int2 c = edge_pair(ei, ((long long)E + e) >> 1, is64);
                int p0 = atomicAdd(&d_cursor[c.x], 1);
                d_edgesrc[p0] = r.x;
                int p1 = atomicAdd(&d_cursor[c.y], 1);
                d_edgesrc[p1] = r.y;
            } else {
                int r = edge_at(ei, e, is64);
                int c = edge_at(ei, (long long)E + e, is64);
                int pos = atomicAdd(&d_cursor[c], 1);
                d_edgesrc[pos] = r;
            }
        } else if (idx < Eh + n) {
            int i = idx - Eh;
            int pos = atomicAdd(&d_cursor[i], 1);
            d_edgesrc[pos] = i;
        }
    } else {
        int i = (b - nbSc) * 256 + threadIdx.x;  // float4 index
        if (i < n16) {
            float di = d_dinv[i >> 4];
            float4 v = ((const float4*)x)[i];
            uint2 w;
            w.x = h2_bits(__floats2half2_rn(di * v.x, di * v.y));
            w.y = h2_bits(__floats2half2_rn(di * v.z, di * v.w));
            ((uint2*)d_xh)[i] = w;
        }
    }
}

// ---------------- aggregation: d_ax[c] = dinv[c] * sum_{e->c} S[src_e] -------
// warp per node, HALF-WARP per edge: 16 lanes x uint2 = one 128B row, so one
// LDG.64 serves 2 edges -> per-edge index/address/loop instructions halve.
// Index loads are half-warp-uniform (1-sector broadcast). fp32 accumulate,
// cross-half SHFL reduce, fp16 out. No shfl in the main loop.
template <bool SECOND>
__global__ void k_agg(int n) {
    int gwarp = (blockIdx.x * blockDim.x + threadIdx.x) >> 5;
    if (gwarp >= n) return;
    int lane = threadIdx.x & 31;
    int hw = lane >> 4;   // which edge of each pair
    int hl = lane & 15;   // uint2 chunk within row (features 4hl..4hl+3)
    int s = d_rowptr[gwarp];
    int e = d_rowptr[gwarp + 1];
    const uint2* __restrict__ X = (const uint2*)(SECOND ? d_gh : d_xh);
    const int* __restrict__ srcs = d_edgesrc;
    float a0 = 0.f, a1 = 0.f, a2 = 0.f, a3 = 0.f;

    #define GATH(idx) do {                                                   \
        uint2 g = X[(idx) * 16 + hl];                                        \
        float2 f0 = __half22float2(*(const __half2*)&g.x);                   \
        float2 f1 = __half22float2(*(const __half2*)&g.y);                   \
        a0 += f0.x; a1 += f0.y; a2 += f1.x; a3 += f1.y;                      \
    } while (0)

    int j = s;
    for (; j + 7 < e; j += 8) {
        int i0 = srcs[j + hw];
        int i1 = srcs[j + 2 + hw];
        int i2 = srcs[j + 4 + hw];
        int i3 = srcs[j + 6 + hw];
        GATH(i0); GATH(i1); GATH(i2); GATH(i3);
    }
    for (; j + 1 < e; j += 2) {
        int i0 = srcs[j + hw];
        GATH(i0);
    }
    if (j < e) {
        int i0 = srcs[j];
        if (hw == 0) GATH(i0);
    }
    #undef GATH

    a0 += __shfl_xor_sync(0xffffffffu, a0, 16);
    a1 += __shfl_xor_sync(0xffffffffu, a1, 16);
    a2 += __shfl_xor_sync(0xffffffffu, a2, 16);
    a3 += __shfl_xor_sync(0xffffffffu, a3, 16);

    if (hw == 0) {
        float di = d_dinv[gwarp];
        uint2 w;
        w.x = h2_bits(__floats2half2_rn(di * a0, di * a1));
        w.y = h2_bits(__floats2half2_rn(di * a2, di * a3));
        ((uint2*)d_ax)[gwarp * 16 + hl] = w;
    }
}

// ---------------- GEMM via tensor cores (HMMA m16n8k16) ----------------------
// reads d_ax (fp16), computes d_ax@W + b; RELU=true -> dinv*relu, fp16 to
// d_gh; RELU=false -> fp32 to OUT. 256 threads, 128 nodes/block.
#define XS_PITCH 72
template <bool RELU>
__global__ __launch_bounds__(256) void k_gemm(const float* __restrict__ W,
                                              const float* __restrict__ bias,
                                              float* __restrict__ OUT, int n) {
    __shared__ __half Xs[128 * XS_PITCH];  // 18 KB
    __shared__ __half Wt[64 * XS_PITCH];   // 9 KB, Wt[f][k] = W[k][f]
    int t = threadIdx.x;
    int base = blockIdx.x * 128;

    // X tile fill via cp.async: 128 nodes * 8 uint4 = 1024, 4 per thread
    for (int i = t; i < 1024; i += 256) {
        int node = i >> 3, q = i & 7;
        void* dst = &Xs[node * XS_PITCH + q * 8];
        if (base + node < n) {
            unsigned ds = (unsigned)__cvta_generic_to_shared(dst);
            const uint4* src = (const uint4*)&d_ax[(base + node) * 32 + q * 4];
            asm volatile("cp.async.ca.shared.global [%0], [%1], 16;"
                         :: "r"(ds), "l"(src));
        } else {
            *(uint4*)dst = make_uint4(0, 0, 0, 0);
        }
    }
    asm volatile("cp.async.commit_group;");
    // W[64,64] fp32 -> Wt fp16 transposed (overlaps with cp.async)
    for (int i = t; i < 4096; i += 256) {
        int k = i >> 6, f = i & 63;
        Wt[f * XS_PITCH + k] = __float2half(W[k * 64 + f]);
    }
    asm volatile("cp.async.wait_group 0;");
    __syncthreads();

    int warp = t >> 5, lane = t & 31;
    int gid = lane >> 2, tig = lane & 3;
    int mbase = warp * 16;

    float c[8][4];
    #pragma unroll
    for (int nt = 0; nt < 8; nt++)
        #pragma unroll
        for (int q = 0; q < 4; q++) c[nt][q] = 0.f;

    #pragma unroll
    for (int kt = 0; kt < 4; kt++) {
        int k0 = kt * 16 + 2 * tig;
        unsigned a0 = *(const unsigned*)&Xs[(mbase + gid) * XS_PITCH + k0];
        unsigned a1 = *(const unsigned*)&Xs[(mbase + gid + 8) * XS_PITCH + k0];
        unsigned a2 = *(const unsigned*)&Xs[(mbase + gid) * XS_PITCH + k0 + 8];
        unsigned a3 = *(const unsigned*)&Xs[(mbase + gid + 8) * XS_PITCH + k0 + 8];
        #pragma unroll
        for (int nt = 0; nt < 8; nt++) {
            unsigned b0 = *(const unsigned*)&Wt[(nt * 8 + gid) * XS_PITCH + k0];
            unsigned b1 = *(const unsigned*)&Wt[(nt * 8 + gid) * XS_PITCH + k0 + 8];
            asm volatile(
                "mma.sync.aligned.m16n8k16.row.col.f32.f16.f16.f32 "
                "{%0,%1,%2,%3}, {%4,%5,%6,%7}, {%8,%9}, {%0,%1,%2,%3};"
                : "+f"(c[nt][0]), "+f"(c[nt][1]), "+f"(c[nt][2]), "+f"(c[nt][3])
                : "r"(a0), "r"(a1), "r"(a2), "r"(a3), "r"(b0), "r"(b1));
        }
    }

    // epilogue: +bias (, relu*dinv); c0,c1 = row gid, c2,c3 = row gid+8
    int node = base + mbase + gid;
    float di0 = (RELU && node < n) ? d_dinv[node] : 0.f;
    float di8 = (RELU && node + 8 < n) ? d_dinv[node + 8] : 0.f;
    #pragma unroll
    for (int nt = 0; nt < 8; nt++) {
        int word = nt * 4 + tig;  // half2/float2 word = features {2w, 2w+1}
        float2 bb = __ldg(&((const float2*)bias)[word]);
        float v0 = c[nt][0] + bb.x, v1 = c[nt][1] + bb.y;
        float v2 = c[nt][2] + bb.x, v3 = c[nt][3] + bb.y;
        if (RELU) {
            v0 = fmaxf(v0, 0.f) * di0; v1 = fmaxf(v1, 0.f) * di0;
            v2 = fmaxf(v2, 0.f) * di8; v3 = fmaxf(v3, 0.f) * di8;
            if (node < n)
                d_gh[node * 32 + word] = h2_bits(__floats2half2_rn(v0, v1));
            if (node + 8 < n)
                d_gh[(node + 8) * 32 + word] = h2_bits(__floats2half2_rn(v2, v3));
        } else {
            if (node < n)
                ((float2*)OUT)[node * 32 + word] = make_float2(v0, v1);
            if (node + 8 < n)
                ((float2*)OUT)[(node + 8) * 32 + word] = make_float2(v2, v3);
        }
    }
}

// ---------------- launch -----------------------------------------------------
extern "C" void kernel_launch(void* const* d_in, const int* in_sizes, int n_in,
                              void* d_out, int out_size) {
    const float* x = (const float*)d_in[0];
    const void* ei = d_in[1];
    const float* W1 = (const float*)d_in[2];
    const float* b1 = (const float*)d_in[3];
    const float* W2 = (const float*)d_in[4];
    const float* b2 = (const float*)d_in[5];
    float* out = (float*)d_out;

    int N = in_sizes[0] / F;          // 100000
    int E = in_sizes[1] / 2;          // 1600000
    int nbS = (N + 511) / 512;        // 196 scan blocks
    int Eh = (E + 1) / 2;
    int nbH = (Eh + 255) / 256;       // hist blocks (2 edges/thread)
    int nbSc = (Eh + N + 255) / 256;  // scatter blocks
    int nbX = (N * 16 + 255) / 256;   // xh blocks

    // graph build (3 kernels; no init — state recycled across calls)
    k_hist<<<nbH, 256>>>(ei, E);
    k_scan<<<nbS, 512>>>(N, nbS, E + N);
    k_scatxh<<<nbSc + nbX, 256>>>(ei, x, E, N, nbSc, N * 16);

    // layer 1: AX = dinv*agg(xh); gh = dinv*relu(AX@W1 + b1)
    k_agg<false><<<(N * 32 + 255) / 256, 256>>>(N);   // profiled slot 4
    k_gemm<true><<<(N + 127) / 128, 256>>>(W1, b1, out /*unused*/, N);

    // layer 2: Ag = dinv*agg(gh); out = Ag@W2 + b2
    k_agg<true><<<(N * 32 + 255) / 256, 256>>>(N);
    k_gemm<false><<<(N + 127) / 128, 256>>>(W2, b2, out, N);
}

// round 15
// speedup vs baseline: 1.0875x; 1.0047x over previous
#include <cuda_runtime.h>
#include <cuda_fp16.h>
#include <cuda_bf16.h>

#define MAXN 100000
#define MAXE 1600000
#define F 64

// ---------------- scratch (static device globals; no allocation) -------------
// Invariant: at entry of every kernel_launch call, d_counts == 0,
// d_scanstate == 0, d_ticket == 0 (true at module load; every call restores).
__device__ int      d_counts[MAXN];        // degree histogram (zeroed by scan)
__device__ int      d_rowptr[MAXN + 1];    // CSR row pointers (by destination)
__device__ int      d_cursor[MAXN];        // scatter cursors
__device__ float    d_dinv[MAXN];          // deg^-1/2
__device__ unsigned long long d_scanstate[512];  // lookback {status:2,val:62}
__device__ unsigned d_ticket;              // scan block ordering ticket
__device__ int      d_edgesrc[MAXE + MAXN];// CSR-by-dst: source index per slot
__device__ unsigned d_xh[MAXN * 32];       // dinv-scaled x, fp16 (32 half2/node)
__device__ unsigned d_ax[MAXN * 32];       // aggregation output (fp16)
__device__ unsigned d_gh[MAXN * 32];       // dinv-scaled layer-1 act (fp16)

__device__ __forceinline__ unsigned h2_bits(__half2 h) {
    union { __half2 h; unsigned u; } cvt;
    cvt.h = h;
    return cvt.u;
}

// ---------------- edge index accessors (runtime dtype) ------------------------
// per-warp dtype detect: int64 indices < 2^31 have zero odd 32-bit words.
__device__ __forceinline__ int detect64(const void* ei, int lane) {
    const unsigned* p = (const unsigned*)ei;
    unsigned v = (lane < 16) ? p[2 * lane + 1] : 0u;
    return __all_sync(0xffffffffu, v == 0u);
}

__device__ __forceinline__ int edge_at(const void* ei, long long idx, int is64) {
    if (is64) return (int)((const long long*)ei)[idx];
    return ((const int*)ei)[idx];
}

__device__ __forceinline__ int2 edge_pair(const void* ei, long long halfidx,
                                          int is64) {
    if (is64) {
        longlong2 v = ((const longlong2*)ei)[halfidx];
        return make_int2((int)v.x, (int)v.y);
    }
    return ((const int2*)ei)[halfidx];
}

// ---------------- hist: degree histogram of destinations, 2 edges/thread -----
__global__ void k_hist(const void* __restrict__ ei, int E) {
    int lane = threadIdx.x & 31;
    int is64 = detect64(ei, lane);
    int e = (blockIdx.x * blockDim.x + threadIdx.x) * 2;
    if (e + 1 < E) {
        int2 c = edge_pair(ei, ((long long)E + e) >> 1, is64);
        atomicAdd(&d_counts[c.x], 1);
        atomicAdd(&d_counts[c.y], 1);
    } else if (e < E) {
        atomicAdd(&d_counts[edge_at(ei, (long long)E + e, is64)], 1);
    }
}

// single-pass scan (decoupled lookback) + fused dinv + counts re-zeroing.
// v = counts[i] + 1 (self loop folded here; counts arrive zero-based).
__global__ void k_scan(int n, int nb, int total) {  // 512 threads/block
    __shared__ unsigned sbid;
    __shared__ int srun;
    __shared__ int ws[16];
    if (threadIdx.x == 0) sbid = atomicAdd(&d_ticket, 1u);
    __syncthreads();
    int bid = (int)sbid;
    int i = bid * 512 + threadIdx.x;
    int lane = threadIdx.x & 31;
    int v = (i < n) ? (d_counts[i] + 1) : 0;
    if (i < n) {
        d_dinv[i] = rsqrtf((float)v);
        d_counts[i] = 0;  // restore invariant for next call
    }
    int x = v;
    #pragma unroll
    for (int d = 1; d < 32; d <<= 1) {
        int y = __shfl_up_sync(0xffffffffu, x, d);
        if (lane >= d) x += y;
    }
    if (lane == 31) ws[threadIdx.x >> 5] = x;
    __syncthreads();
    if (threadIdx.x < 16) {
        int z = ws[threadIdx.x];
        #pragma unroll
        for (int d = 1; d < 16; d <<= 1) {
            int y = __shfl_up_sync(0xffffu, z, d);
            if ((int)threadIdx.x >= d) z += y;
        }
        ws[threadIdx.x] = z;
    }
    __syncthreads();
    int off = (threadIdx.x >= 32) ? ws[(threadIdx.x >> 5) - 1] : 0;
    int incl = x + off;

    if (threadIdx.x == 511) {
        int btotal = incl;
        if (bid == 0) {
            atomicExch(&d_scanstate[0],
                       (2ull << 62) | (unsigned long long)(unsigned)btotal);
            srun = 0;
        } else {
            atomicExch(&d_scanstate[bid],
                       (1ull << 62) | (unsigned long long)(unsigned)btotal);
            int running = 0;
            int j = bid - 1;
            while (true) {
                unsigned long long s;
                do {
                    s = *(volatile unsigned long long*)&d_scanstate[j];
                } while ((s >> 62) == 0ull);
                int val = (int)(s & 0xffffffffull);
                running += val;
                if ((s >> 62) == 2ull) break;
                j--;
            }
            atomicExch(&d_scanstate[bid],
                       (2ull << 62) | (unsigned long long)(unsigned)(running + btotal));
            srun = running;
        }
    }
    __syncthreads();
    int run = srun;
    if (i < n) {
        int r = incl - v + run;
        d_rowptr[i] = r;
        d_cursor[i] = r;
    }
    if (i == 0) d_rowptr[n] = total;
}

// fused: scatter src indices (blocks [0,nbSc)) + dinv-scaled x->fp16 (rest).
// Block 0 additionally re-zeroes scanstate + ticket (scan is complete).
__global__ void k_scatxh(const void* __restrict__ ei, const float* __restrict__ x,
                         int E, int n, int nbSc, int n16) {
    int b = blockIdx.x;
    if (b == 0) {
        for (int i = threadIdx.x; i < 512; i += 256) d_scanstate[i] = 0ull;
        if (threadIdx.x == 0) d_ticket = 0u;
    }
    if (b < nbSc) {
        int lane = threadIdx.x & 31;
        int is64 = detect64(ei, lane);
        int idx = b * 256 + threadIdx.x;
        int Eh = (E + 1) >> 1;
        if (idx < Eh) {
            int e = idx * 2;
            if (e + 1 < E) {
                int2 r = edge_pair(ei, (long long)e >> 1, is64);
                int2 c = edge_pair(ei, ((long long)E + e) >> 1, is64);
                int p0 = atomicAdd(&d_cursor[c.x], 1);
                d_edgesrc[p0] = r.x;
                int p1 = atomicAdd(&d_cursor[c.y], 1);
                d_edgesrc[p1] = r.y;
            } else {
                int r = edge_at(ei, e, is64);
                int c = edge_at(ei, (long long)E + e, is64);
                int pos = atomicAdd(&d_cursor[c], 1);
                d_edgesrc[pos] = r;
            }
        } else if (idx < Eh + n) {
            int i = idx - Eh;
            int pos = atomicAdd(&d_cursor[i], 1);
            d_edgesrc[pos] = i;
        }
    } else {
        int i = (b - nbSc) * 256 + threadIdx.x;  // float4 index
        if (i < n16) {
            float di = d_dinv[i >> 4];
            float4 v = ((const float4*)x)[i];
            uint2 w;
            w.x = h2_bits(__floats2half2_rn(di * v.x, di * v.y));
            w.y = h2_bits(__floats2half2_rn(di * v.z, di * v.w));
            ((uint2*)d_xh)[i] = w;
        }
    }
}

// ---------------- aggregation: d_ax[c] = dinv[c] * sum_{e->c} S[src_e] -------
// warp per node, half-warp per edge (one LDG.64 = 2 edges). Inner accumulation
// in fp16 via HADD2 (1 instr per gathered half2 vs 2cvt+2add); the <=4-term
// fp16 partial is flushed to fp32 every 8-edge iteration. Remainder edges
// accumulate in pure fp32. Cross-half SHFL reduce, fp16 out.
template <bool SECOND>
__global__ void k_agg(int n) {
    int gwarp = (blockIdx.x * blockDim.x + threadIdx.x) >> 5;
    if (gwarp >= n) return;
    int lane = threadIdx.x & 31;
    int hw = lane >> 4;   // which edge of each pair
    int hl = lane & 15;   // uint2 chunk within row (features 4hl..4hl+3)
    int s = d_rowptr[gwarp];
    int e = d_rowptr[gwarp + 1];
    const uint2* __restrict__ X = (const uint2*)(SECOND ? d_gh : d_xh);
    const int* __restrict__ srcs = d_edgesrc;
    float a0 = 0.f, a1 = 0.f, a2 = 0.f, a3 = 0.f;
    const __half2 hz = __float2half2_rn(0.f);

    int j = s;
    for (; j + 7 < e; j += 8) {
        int i0 = srcs[j + hw];
        int i1 = srcs[j + 2 + hw];
        int i2 = srcs[j + 4 + hw];
        int i3 = srcs[j + 6 + hw];
        uint2 g0 = X[i0 * 16 + hl];
        uint2 g1 = X[i1 * 16 + hl];
        uint2 g2 = X[i2 * 16 + hl];
        uint2 g3 = X[i3 * 16 + hl];
        // fp16 tree accumulation: <=4-term chains, flushed each iteration
        __half2 hx = __hadd2(__hadd2(*(const __half2*)&g0.x, *(const __half2*)&g1.x),
                             __hadd2(*(const __half2*)&g2.x, *(const __half2*)&g3.x));
        __half2 hy = __hadd2(__hadd2(*(const __half2*)&g0.y, *(const __half2*)&g1.y),
                             __hadd2(*(const __half2*)&g2.y, *(const __half2*)&g3.y));
        float2 fx = __half22float2(hx);
        float2 fy = __half22float2(hy);
        a0 += fx.x; a1 += fx.y; a2 += fy.x; a3 += fy.y;
    }
    for (; j + 1 < e; j += 2) {
        int i0 = srcs[j + hw];
        uint2 g = X[i0 * 16 + hl];
        float2 f0 = __half22float2(*(const __half2*)&g.x);
        float2 f1 = __half22float2(*(const __half2*)&g.y);
        a0 += f0.x; a1 += f0.y; a2 += f1.x; a3 += f1.y;
    }
    if (j < e) {
        int i0 = srcs[j];
        if (hw == 0) {
            uint2 g = X[i0 * 16 + hl];
            float2 f0 = __half22float2(*(const __half2*)&g.x);
            float2 f1 = __half22float2(*(const __half2*)&g.y);
            a0 += f0.x; a1 += f0.y; a2 += f1.x; a3 += f1.y;
        }
    }

    a0 += __shfl_xor_sync(0xffffffffu, a0, 16);
    a1 += __shfl_xor_sync(0xffffffffu, a1, 16);
    a2 += __shfl_xor_sync(0xffffffffu, a2, 16);
    a3 += __shfl_xor_sync(0xffffffffu, a3, 16);

    if (hw == 0) {
        float di = d_dinv[gwarp];
        uint2 w;
        w.x = h2_bits(__floats2half2_rn(di * a0, di * a1));
        w.y = h2_bits(__floats2half2_rn(di * a2, di * a3));
        ((uint2*)d_ax)[gwarp * 16 + hl] = w;
    }
}

// ---------------- GEMM via tensor cores (HMMA m16n8k16) ----------------------
// reads d_ax (fp16), computes d_ax@W + b; RELU=true -> dinv*relu, fp16 to
// d_gh; RELU=false -> fp32 to OUT. 256 threads, 128 nodes/block.
#define XS_PITCH 72
template <bool RELU>
__global__ __launch_bounds__(256) void k_gemm(const float* __restrict__ W,
                                              const float* __restrict__ bias,
                                              float* __restrict__ OUT, int n) {
    __shared__ __half Xs[128 * XS_PITCH];  // 18 KB
    __shared__ __half Wt[64 * XS_PITCH];   // 9 KB, Wt[f][k] = W[k][f]
    int t = threadIdx.x;
    int base = blockIdx.x * 128;

    // X tile fill via cp.async: 128 nodes * 8 uint4 = 1024, 4 per thread
    for (int i = t; i < 1024; i += 256) {
        int node = i >> 3, q = i & 7;
        void* dst = &Xs[node * XS_PITCH + q * 8];
        if (base + node < n) {
            unsigned ds = (unsigned)__cvta_generic_to_shared(dst);
            const uint4* src = (const uint4*)&d_ax[(base + node) * 32 + q * 4];
            asm volatile("cp.async.ca.shared.global [%0], [%1], 16;"
                         :: "r"(ds), "l"(src));
        } else {
            *(uint4*)dst = make_uint4(0, 0, 0, 0);
        }
    }
    asm volatile("cp.async.commit_group;");
    // W[64,64] fp32 -> Wt fp16 transposed (overlaps with cp.async)
    for (int i = t; i < 4096; i += 256) {
        int k = i >> 6, f = i & 63;
        Wt[f * XS_PITCH + k] = __float2half(W[k * 64 + f]);
    }
    asm volatile("cp.async.wait_group 0;");
    __syncthreads();

    int warp = t >> 5, lane = t & 31;
    int gid = lane >> 2, tig = lane & 3;
    int mbase = warp * 16;

    float c[8][4];
    #pragma unroll
    for (int nt = 0; nt < 8; nt++)
        #pragma unroll
        for (int q = 0; q < 4; q++) c[nt][q] = 0.f;

    #pragma unroll
    for (int kt = 0; kt < 4; kt++) {
        int k0 = kt * 16 + 2 * tig;
        unsigned a0 = *(const unsigned*)&Xs[(mbase + gid) * XS_PITCH + k0];
        unsigned a1 = *(const unsigned*)&Xs[(mbase + gid + 8) * XS_PITCH + k0];
        unsigned a2 = *(const unsigned*)&Xs[(mbase + gid) * XS_PITCH + k0 + 8];
        unsigned a3 = *(const unsigned*)&Xs[(mbase + gid + 8) * XS_PITCH + k0 + 8];
        #pragma unroll
        for (int nt = 0; nt < 8; nt++) {
            unsigned b0 = *(const unsigned*)&Wt[(nt * 8 + gid) * XS_PITCH + k0];
            unsigned b1 = *(const unsigned*)&Wt[(nt * 8 + gid) * XS_PITCH + k0 + 8];
            asm volatile(
                "mma.sync.aligned.m16n8k16.row.col.f32.f16.f16.f32 "
                "{%0,%1,%2,%3}, {%4,%5,%6,%7}, {%8,%9}, {%0,%1,%2,%3};"
                : "+f"(c[nt][0]), "+f"(c[nt][1]), "+f"(c[nt][2]), "+f"(c[nt][3])
                : "r"(a0), "r"(a1), "r"(a2), "r"(a3), "r"(b0), "r"(b1));
        }
    }

    // epilogue: +bias (, relu*dinv); c0,c1 = row gid, c2,c3 = row gid+8
    int node = base + mbase + gid;
    float di0 = (RELU && node < n) ? d_dinv[node] : 0.f;
    float di8 = (RELU && node + 8 < n) ? d_dinv[node + 8] : 0.f;
    #pragma unroll
    for (int nt = 0; nt < 8; nt++) {
        int word = nt * 4 + tig;  // half2/float2 word = features {2w, 2w+1}
        float2 bb = __ldg(&((const float2*)bias)[word]);
        float v0 = c[nt][0] + bb.x, v1 = c[nt][1] + bb.y;
        float v2 = c[nt][2] + bb.x, v3 = c[nt][3] + bb.y;
        if (RELU) {
            v0 = fmaxf(v0, 0.f) * di0; v1 = fmaxf(v1, 0.f) * di0;
            v2 = fmaxf(v2, 0.f) * di8; v3 = fmaxf(v3, 0.f) * di8;
            if (node < n)
                d_gh[node * 32 + word] = h2_bits(__floats2half2_rn(v0, v1));
            if (node + 8 < n)
                d_gh[(node + 8) * 32 + word] = h2_bits(__floats2half2_rn(v2, v3));
        } else {
            if (node < n)
                ((float2*)OUT)[node * 32 + word] = make_float2(v0, v1);
            if (node + 8 < n)
                ((float2*)OUT)[(node + 8) * 32 + word] = make_float2(v2, v3);
        }
    }
}

// ---------------- launch -----------------------------------------------------
extern "C" void kernel_launch(void* const* d_in, const int* in_sizes, int n_in,
                              void* d_out, int out_size) {
    const float* x = (const float*)d_in[0];
    const void* ei = d_in[1];
    const float* W1 = (const float*)d_in[2];
    const float* b1 = (const float*)d_in[3];
    const float* W2 = (const float*)d_in[4];
    const float* b2 = (const float*)d_in[5];
    float* out = (float*)d_out;

    int N = in_sizes[0] / F;          // 100000
    int E = in_sizes[1] / 2;          // 1600000
    int nbS = (N + 511) / 512;        // 196 scan blocks
    int Eh = (E + 1) / 2;
    int nbH = (Eh + 255) / 256;       // hist blocks (2 edges/thread)
    int nbSc = (Eh + N + 255) / 256;  // scatter blocks
    int nbX = (N * 16 + 255) / 256;   // xh blocks

    // graph build (3 kernels; no init — state recycled across calls)
    k_hist<<<nbH, 256>>>(ei, E);
    k_scan<<<nbS, 512>>>(N, nbS, E + N);
    k_scatxh<<<nbSc + nbX, 256>>>(ei, x, E, N, nbSc, N * 16);

    // layer 1: AX = dinv*agg(xh); gh = dinv*relu(AX@W1 + b1)
    k_agg<false><<<(N * 32 + 255) / 256, 256>>>(N);   // profiled slot 4
    k_gemm<true><<<(N + 127) / 128, 256>>>(W1, b1, out /*unused*/, N);

    // layer 2: Ag = dinv*agg(gh); out = Ag@W2 + b2
    k_agg<true><<<(N * 32 + 255) / 256, 256>>>(N);
    k_gemm<false><<<(N + 127) / 128, 256>>>(W2, b2, out, N);
}